// round 15
// baseline (speedup 1.0000x reference)
#include <cuda_runtime.h>
#include <cuda_fp16.h>
#include <cuda_bf16.h>
#include <cstdint>

#define N_NODES 100000
#define N_EDGES 3200000
#define IN_CH   512
#define OUT_CH  64
#define SCAN_B  98          // ceil(N_NODES / 1024)
#define EPT     8           // edges per thread in hist/scatter

// ---- scratch: __device__ globals only ----
__device__ int g_is64;
__device__ __align__(16) int    g_cnt   [N_NODES];
__device__ __align__(16) int    g_rowptr[N_NODES + 1];
__device__ __align__(16) int    g_bsum  [SCAN_B];
__device__ __align__(16) int    g_bbase [SCAN_B];
__device__ __align__(16) float  g_dinv  [N_NODES];
__device__ __align__(16) int    g_ecol  [N_EDGES];
__device__ __align__(16) float  g_u0    [(size_t)N_NODES * OUT_CH]; // raw xW (fp32)
__device__ __align__(16) __half g_h0    [(size_t)N_NODES * OUT_CH]; // h0s = dinv*(xW)
__device__ __align__(16) __half g_h1    [(size_t)N_NODES * OUT_CH]; // h1s
__device__ __align__(16) __nv_bfloat16 g_Wth[OUT_CH][IN_CH];
__device__ __align__(16) __nv_bfloat16 g_Wtl[OUT_CH][IN_CH];

// ---------------- zero counts + dtype probe (one launch) ----------------
__global__ void zero_detect_kernel(const int* __restrict__ buf) {
    int i = blockIdx.x * blockDim.x + threadIdx.x;
    if (i < N_NODES) g_cnt[i] = 0;
    if (blockIdx.x == 0 && threadIdx.x == 0) {
        int any_odd_nonzero = 0;
        for (int j = 0; j < 2048; j++) {
            if (buf[2 * j + 1] != 0) { any_odd_nonzero = 1; break; }
        }
        g_is64 = any_odd_nonzero ? 0 : 1;
    }
}

// load EPT consecutive edges starting at e0 with batched vector loads
__device__ __forceinline__ void load_edge8(const void* buf, int e0,
                                           int r[EPT], int c[EPT]) {
    if (g_is64) {
        const longlong2* pr = (const longlong2*)((const long long*)buf + e0);
        const longlong2* pc = (const longlong2*)((const long long*)buf + N_EDGES + e0);
        longlong2 rr[4], cc[4];
        #pragma unroll
        for (int j = 0; j < 4; j++) rr[j] = pr[j];
        #pragma unroll
        for (int j = 0; j < 4; j++) cc[j] = pc[j];
        #pragma unroll
        for (int j = 0; j < 4; j++) {
            r[2 * j] = (int)rr[j].x; r[2 * j + 1] = (int)rr[j].y;
            c[2 * j] = (int)cc[j].x; c[2 * j + 1] = (int)cc[j].y;
        }
    } else {
        const int4* pr = (const int4*)((const int*)buf + e0);
        const int4* pc = (const int4*)((const int*)buf + N_EDGES + e0);
        int4 rr[2], cc[2];
        #pragma unroll
        for (int j = 0; j < 2; j++) rr[j] = pr[j];
        #pragma unroll
        for (int j = 0; j < 2; j++) cc[j] = pc[j];
        r[0] = rr[0].x; r[1] = rr[0].y; r[2] = rr[0].z; r[3] = rr[0].w;
        r[4] = rr[1].x; r[5] = rr[1].y; r[6] = rr[1].z; r[7] = rr[1].w;
        c[0] = cc[0].x; c[1] = cc[0].y; c[2] = cc[0].z; c[3] = cc[0].w;
        c[4] = cc[1].x; c[5] = cc[1].y; c[6] = cc[1].z; c[7] = cc[1].w;
    }
}

__global__ void hist_kernel(const void* __restrict__ buf) {
    int t = blockIdx.x * blockDim.x + threadIdx.x;
    int e0 = t * EPT;
    if (e0 >= N_EDGES) return;
    int r[EPT], c[EPT];
    load_edge8(buf, e0, r, c);
    #pragma unroll
    for (int j = 0; j < EPT; j++) {
        if ((unsigned)r[j] < N_NODES && (unsigned)c[j] < N_NODES && r[j] != c[j])
            atomicAdd(&g_cnt[r[j]], 1);
    }
}

// ---------------- 3-phase scan: g_cnt -> g_rowptr (+ dinv in phase C) -------
__global__ __launch_bounds__(1024) void scanA_kernel() {
    __shared__ int wsum[32];
    int b = blockIdx.x, t = threadIdx.x;
    int i = b * 1024 + t;
    int v = (i < N_NODES) ? g_cnt[i] : 0;
    int lane = t & 31, wid = t >> 5;
    int s = v;
    #pragma unroll
    for (int off = 16; off > 0; off >>= 1) s += __shfl_xor_sync(~0u, s, off);
    if (lane == 0) wsum[wid] = s;
    __syncthreads();
    if (wid == 0) {
        int w = wsum[lane];
        #pragma unroll
        for (int off = 16; off > 0; off >>= 1) w += __shfl_xor_sync(~0u, w, off);
        if (lane == 0) g_bsum[b] = w;
    }
}

__global__ void scanB_kernel() {
    int lane = threadIdx.x;                 // 32 threads
    int v[4];
    int local = 0;
    #pragma unroll
    for (int j = 0; j < 4; j++) {
        int i = lane * 4 + j;
        v[j] = (i < SCAN_B) ? g_bsum[i] : 0;
        local += v[j];
    }
    int incl = local;
    #pragma unroll
    for (int off = 1; off < 32; off <<= 1) {
        int n = __shfl_up_sync(~0u, incl, off);
        if (lane >= off) incl += n;
    }
    int run = incl - local;
    #pragma unroll
    for (int j = 0; j < 4; j++) {
        int i = lane * 4 + j;
        if (i < SCAN_B) g_bbase[i] = run;
        run += v[j];
    }
    if (lane == 31) g_rowptr[N_NODES] = incl;
}

__global__ __launch_bounds__(1024) void scanC_kernel() {
    __shared__ int wsum[32];
    int b = blockIdx.x, t = threadIdx.x;
    int i = b * 1024 + t;
    int v = (i < N_NODES) ? g_cnt[i] : 0;
    int lane = t & 31, wid = t >> 5;
    int incl = v;
    #pragma unroll
    for (int off = 1; off < 32; off <<= 1) {
        int n = __shfl_up_sync(~0u, incl, off);
        if (lane >= off) incl += n;
    }
    if (lane == 31) wsum[wid] = incl;
    __syncthreads();
    if (wid == 0) {
        int s = wsum[lane];
        #pragma unroll
        for (int off = 1; off < 32; off <<= 1) {
            int n = __shfl_up_sync(~0u, s, off);
            if (lane >= off) s += n;
        }
        wsum[lane] = s;
    }
    __syncthreads();
    if (i < N_NODES) {
        int excl = incl - v + (wid > 0 ? wsum[wid - 1] : 0) + g_bbase[b];
        g_rowptr[i] = excl;
        g_dinv[i]   = rsqrtf((float)v + 1.0f);
    }
}

__global__ void scatter_kernel(const void* __restrict__ buf) {
    int t = blockIdx.x * blockDim.x + threadIdx.x;
    int e0 = t * EPT;
    if (e0 >= N_EDGES) return;
    int r[EPT], c[EPT];
    load_edge8(buf, e0, r, c);
    #pragma unroll
    for (int j = 0; j < EPT; j++) {
        if ((unsigned)r[j] < N_NODES && (unsigned)c[j] < N_NODES && r[j] != c[j]) {
            int left = atomicSub(&g_cnt[r[j]], 1);
            g_ecol[g_rowptr[r[j]] + left - 1] = c[j];
        }
    }
}

// ---------------- W split/transpose ----------------
__global__ void wsplit_kernel(const float* __restrict__ W) {
    int t = blockIdx.x * blockDim.x + threadIdx.x;
    if (t >= IN_CH * OUT_CH) return;
    int n = t / IN_CH;
    int k = t % IN_CH;
    float v = W[(size_t)k * OUT_CH + n];
    __nv_bfloat16 hi = __float2bfloat16(v);
    __nv_bfloat16 lo = __float2bfloat16(v - __bfloat162float(hi));
    g_Wth[n][k] = hi;
    g_Wtl[n][k] = lo;
}

// ---------------- GEMM: g_u0 = x @ W (raw fp32) -----------------------------
#define GBM 128
#define GBK 32
#define SAS 17

__device__ __forceinline__ uint32_t pack_bf16(__nv_bfloat16 a, __nv_bfloat16 b) {
    return (uint32_t)__bfloat16_as_ushort(a) | ((uint32_t)__bfloat16_as_ushort(b) << 16);
}

__device__ __forceinline__ void mma16816(float c[4], const uint32_t a[4],
                                         const uint32_t b[2]) {
    asm volatile(
        "mma.sync.aligned.m16n8k16.row.col.f32.bf16.bf16.f32 "
        "{%0,%1,%2,%3}, {%4,%5,%6,%7}, {%8,%9}, {%0,%1,%2,%3};"
        : "+f"(c[0]), "+f"(c[1]), "+f"(c[2]), "+f"(c[3])
        : "r"(a[0]), "r"(a[1]), "r"(a[2]), "r"(a[3]), "r"(b[0]), "r"(b[1]));
}

__global__ __launch_bounds__(256, 2) void gemm_mma_kernel(const float* __restrict__ x) {
    __shared__ uint32_t sAh[GBM][SAS];
    __shared__ uint32_t sAl[GBM][SAS];
    __shared__ uint32_t sBh[OUT_CH][SAS];
    __shared__ uint32_t sBl[OUT_CH][SAS];

    int tid  = threadIdx.x;
    int wid  = tid >> 5, lane = tid & 31;
    int wm   = wid & 3,  wn   = wid >> 2;
    int grp  = lane >> 2, t4  = lane & 3;
    int m0   = blockIdx.x * GBM;

    float c[2][4][4];
    #pragma unroll
    for (int i = 0; i < 2; i++)
        #pragma unroll
        for (int j = 0; j < 4; j++)
            #pragma unroll
            for (int k = 0; k < 4; k++) c[i][j][k] = 0.0f;

    float4   xr[4];
    uint32_t wh[4], wl[4];

    #pragma unroll
    for (int i = 0; i < 4; i++) {
        int idx = tid + i * 256;
        int row = idx >> 3, f4 = idx & 7;
        xr[i] = make_float4(0.f, 0.f, 0.f, 0.f);
        if (m0 + row < N_NODES)
            xr[i] = *(const float4*)(x + (size_t)(m0 + row) * IN_CH + f4 * 4);
        int n = idx >> 4, kp = idx & 15;
        wh[i] = ((const uint32_t*)&g_Wth[n][0])[kp];
        wl[i] = ((const uint32_t*)&g_Wtl[n][0])[kp];
    }

    for (int k0 = 0; k0 < IN_CH; k0 += GBK) {
        #pragma unroll
        for (int i = 0; i < 4; i++) {
            int idx = tid + i * 256;
            int row = idx >> 3, f4 = idx & 7;
            float4 v = xr[i];
            __nv_bfloat16 hx = __float2bfloat16(v.x);
            __nv_bfloat16 hy = __float2bfloat16(v.y);
            __nv_bfloat16 hz = __float2bfloat16(v.z);
            __nv_bfloat16 hw = __float2bfloat16(v.w);
            sAh[row][f4 * 2]     = pack_bf16(hx, hy);
            sAh[row][f4 * 2 + 1] = pack_bf16(hz, hw);
            __nv_bfloat16 lx = __float2bfloat16(v.x - __bfloat162float(hx));
            __nv_bfloat16 ly = __float2bfloat16(v.y - __bfloat162float(hy));
            __nv_bfloat16 lz = __float2bfloat16(v.z - __bfloat162float(hz));
            __nv_bfloat16 lw = __float2bfloat16(v.w - __bfloat162float(hw));
            sAl[row][f4 * 2]     = pack_bf16(lx, ly);
            sAl[row][f4 * 2 + 1] = pack_bf16(lz, lw);
            int n = idx >> 4, kp = idx & 15;
            sBh[n][kp] = wh[i];
            sBl[n][kp] = wl[i];
        }
        __syncthreads();

        int kn = k0 + GBK;
        if (kn < IN_CH) {
            #pragma unroll
            for (int i = 0; i < 4; i++) {
                int idx = tid + i * 256;
                int row = idx >> 3, f4 = idx & 7;
                xr[i] = make_float4(0.f, 0.f, 0.f, 0.f);
                if (m0 + row < N_NODES)
                    xr[i] = *(const float4*)(x + (size_t)(m0 + row) * IN_CH + kn + f4 * 4);
                int n = idx >> 4, kp = idx & 15;
                wh[i] = ((const uint32_t*)&g_Wth[n][kn])[kp];
                wl[i] = ((const uint32_t*)&g_Wtl[n][kn])[kp];
            }
        }

        #pragma unroll
        for (int kt = 0; kt < 2; kt++) {
            int kp0 = kt * 8;
            uint32_t ah[2][4], al[2][4];
            #pragma unroll
            for (int mt = 0; mt < 2; mt++) {
                int r = wm * 32 + mt * 16 + grp;
                ah[mt][0] = sAh[r][kp0 + t4];
                ah[mt][1] = sAh[r + 8][kp0 + t4];
                ah[mt][2] = sAh[r][kp0 + t4 + 4];
                ah[mt][3] = sAh[r + 8][kp0 + t4 + 4];
                al[mt][0] = sAl[r][kp0 + t4];
                al[mt][1] = sAl[r + 8][kp0 + t4];
                al[mt][2] = sAl[r][kp0 + t4 + 4];
                al[mt][3] = sAl[r + 8][kp0 + t4 + 4];
            }
            uint32_t bh[4][2], bl[4][2];
            #pragma unroll
            for (int nt = 0; nt < 4; nt++) {
                int n = wn * 32 + nt * 8 + grp;
                bh[nt][0] = sBh[n][kp0 + t4];
                bh[nt][1] = sBh[n][kp0 + t4 + 4];
                bl[nt][0] = sBl[n][kp0 + t4];
                bl[nt][1] = sBl[n][kp0 + t4 + 4];
            }
            #pragma unroll
            for (int mt = 0; mt < 2; mt++)
                #pragma unroll
                for (int nt = 0; nt < 4; nt++) {
                    mma16816(c[mt][nt], ah[mt], bh[nt]);
                    mma16816(c[mt][nt], ah[mt], bl[nt]);
                    mma16816(c[mt][nt], al[mt], bh[nt]);
                }
        }
        __syncthreads();
    }

    #pragma unroll
    for (int mt = 0; mt < 2; mt++) {
        int r0 = m0 + wm * 32 + mt * 16 + grp;
        int r1 = r0 + 8;
        #pragma unroll
        for (int nt = 0; nt < 4; nt++) {
            int col = wn * 32 + nt * 8 + t4 * 2;
            if (r0 < N_NODES) {
                float2 v = make_float2(c[mt][nt][0], c[mt][nt][1]);
                *(float2*)(g_u0 + (size_t)r0 * OUT_CH + col) = v;
            }
            if (r1 < N_NODES) {
                float2 v = make_float2(c[mt][nt][2], c[mt][nt][3]);
                *(float2*)(g_u0 + (size_t)r1 * OUT_CH + col) = v;
            }
        }
    }
}

// h0 = fp16( dinv[node] * u0 )   (needs GEMM + scanC; runs ∥ scatter)
__global__ void scale_h0_kernel() {
    int idx = blockIdx.x * blockDim.x + threadIdx.x;   // 4-elem chunk index
    const int total = N_NODES * OUT_CH / 4;
    if (idx >= total) return;
    int node = idx >> 4;
    float s = g_dinv[node];
    float4 v = *(const float4*)(g_u0 + (size_t)idx * 4);
    __half2 h0 = __floats2half2_rn(v.x * s, v.y * s);
    __half2 h1 = __floats2half2_rn(v.z * s, v.w * s);
    uint2 u;
    u.x = *(uint32_t*)&h0;
    u.y = *(uint32_t*)&h1;
    *(uint2*)(g_h0 + (size_t)idx * 4) = u;
}

// ---------------- gather: fp16 rows, 8 lanes/edge (4 edges/warp-instr),
// 4-slot pipelined ecol prefetch (16 edges in flight per warp) --------------
// MODE 0: hin=g_h0, hout=g_h1 (fp16), scale=d^2
// MODE 1: hin=g_h1, hout=outp (fp32), scale=d
template <int MODE>
__global__ __launch_bounds__(256) void gather_kernel(float* __restrict__ outp) {
    int node = (int)((blockIdx.x * blockDim.x + threadIdx.x) >> 5);
    if (node >= N_NODES) return;
    int lane = threadIdx.x & 31;

    const __half* __restrict__ hin = (MODE == 0) ? g_h0 : g_h1;

    int start = g_rowptr[node];
    int end   = g_rowptr[node + 1];
    int sub  = lane & 7;                // 8-lane group position
    int ch   = sub << 3;                // half offset: 0..56 (uint4 = 8 halves)
    int eoff = lane >> 3;               // 0..3: edge slot within warp

    float acc[8];
    #pragma unroll
    for (int i = 0; i < 8; i++) acc[i] = 0.0f;

    int e0 = start + eoff;
    int c[4];
    #pragma unroll
    for (int j = 0; j < 4; j++) {
        int e = e0 + j * 4;
        c[j] = (e < end) ? g_ecol[e] : -1;
    }
    for (int base = e0; base < end; base += 16) {
        int cn[4];
        #pragma unroll
        for (int j = 0; j < 4; j++) {
            int e = base + 16 + j * 4;
            cn[j] = (e < end) ? g_ecol[e] : -1;
        }
        #pragma unroll
        for (int j = 0; j < 4; j++) {
            if (c[j] >= 0) {
                uint4 u = *(const uint4*)(hin + (size_t)c[j] * OUT_CH + ch);
                float2 f;
                f = __half22float2(*(__half2*)&u.x); acc[0] += f.x; acc[1] += f.y;
                f = __half22float2(*(__half2*)&u.y); acc[2] += f.x; acc[3] += f.y;
                f = __half22float2(*(__half2*)&u.z); acc[4] += f.x; acc[5] += f.y;
                f = __half22float2(*(__half2*)&u.w); acc[6] += f.x; acc[7] += f.y;
            }
            c[j] = cn[j];
        }
    }

    // combine the 4 edge-slots (xor 8, xor 16)
    #pragma unroll
    for (int i = 0; i < 8; i++) {
        acc[i] += __shfl_xor_sync(0xFFFFFFFFu, acc[i], 8);
        acc[i] += __shfl_xor_sync(0xFFFFFFFFu, acc[i], 16);
    }

    if (lane < 8) {
        float d = g_dinv[node];
        float s = (MODE == 0) ? d * d : d;
        uint4 su = *(const uint4*)(hin + (size_t)node * OUT_CH + ch);
        float2 f;
        f = __half22float2(*(__half2*)&su.x); acc[0] += f.x; acc[1] += f.y;
        f = __half22float2(*(__half2*)&su.y); acc[2] += f.x; acc[3] += f.y;
        f = __half22float2(*(__half2*)&su.z); acc[4] += f.x; acc[5] += f.y;
        f = __half22float2(*(__half2*)&su.w); acc[6] += f.x; acc[7] += f.y;
        #pragma unroll
        for (int i = 0; i < 8; i++) acc[i] *= s;

        if (MODE == 0) {
            __half2 o[4];
            #pragma unroll
            for (int j = 0; j < 4; j++)
                o[j] = __floats2half2_rn(acc[2 * j], acc[2 * j + 1]);
            *(uint4*)(g_h1 + (size_t)node * OUT_CH + ch) = *(uint4*)o;
        } else {
            float* dst = outp + (size_t)node * OUT_CH + ch;
            *(float4*)(dst)     = make_float4(acc[0], acc[1], acc[2], acc[3]);
            *(float4*)(dst + 4) = make_float4(acc[4], acc[5], acc[6], acc[7]);
        }
    }
}

extern "C" void kernel_launch(void* const* d_in, const int* in_sizes, int n_in,
                              void* d_out, int out_size) {
    const void*  edge_index = d_in[0];               // [2, N_EDGES] int32 or int64
    const float* x          = (const float*)d_in[1]; // [N_NODES, 512]
    const float* W          = (const float*)d_in[2]; // [512, 64]
    float*       out        = (float*)d_out;         // [N_NODES, 64]

    cudaStream_t s1;
    cudaEvent_t  evRoot, evScan, evScale;
    cudaStreamCreateWithFlags(&s1, cudaStreamNonBlocking);
    cudaEventCreateWithFlags(&evRoot,  cudaEventDisableTiming);
    cudaEventCreateWithFlags(&evScan,  cudaEventDisableTiming);
    cudaEventCreateWithFlags(&evScale, cudaEventDisableTiming);

    cudaEventRecord(evRoot, 0);
    cudaStreamWaitEvent(s1, evRoot, 0);

    // s1: weight split + raw GEMM (needs only x, W)
    wsplit_kernel<<<(IN_CH * OUT_CH + 255) / 256, 256, 0, s1>>>(W);
    gemm_mma_kernel<<<(N_NODES + GBM - 1) / GBM, 256, 0, s1>>>(x);

    // s0: CSR build chain (8 edges per thread)
    const int eblocks = (N_EDGES / EPT + 255) / 256;
    zero_detect_kernel<<<(N_NODES + 255) / 256, 256>>>((const int*)edge_index);
    hist_kernel<<<eblocks, 256>>>(edge_index);
    scanA_kernel<<<SCAN_B, 1024>>>();
    scanB_kernel<<<1, 32>>>();
    scanC_kernel<<<SCAN_B, 1024>>>();
    cudaEventRecord(evScan, 0);

    // s1: scale_h0 (GEMM done on s1; scanC via event) — overlaps scatter
    cudaStreamWaitEvent(s1, evScan, 0);
    const int vec_total = N_NODES * OUT_CH / 4;
    scale_h0_kernel<<<(vec_total + 255) / 256, 256, 0, s1>>>();
    cudaEventRecord(evScale, s1);

    // s0: scatter ∥ scale_h0, then join and run the two hops
    scatter_kernel<<<eblocks, 256>>>(edge_index);
    cudaStreamWaitEvent(0, evScale, 0);

    const int blocks = (N_NODES * 32 + 255) / 256;
    gather_kernel<0><<<blocks, 256>>>(nullptr);
    gather_kernel<1><<<blocks, 256>>>(out);
}

// round 16
// speedup vs baseline: 1.0261x; 1.0261x over previous
#include <cuda_runtime.h>
#include <cuda_fp16.h>
#include <cuda_bf16.h>
#include <cstdint>

#define N_NODES 100000
#define N_EDGES 3200000
#define IN_CH   512
#define OUT_CH  64
#define SCAN_B  98          // ceil(N_NODES / 1024)

// ---- scratch: __device__ globals only ----
__device__ int g_is64;
__device__ __align__(16) int    g_cnt   [N_NODES];
__device__ __align__(16) int    g_cur   [N_NODES];
__device__ __align__(16) int    g_rowptr[N_NODES + 1];
__device__ __align__(16) int    g_bsum  [SCAN_B];
__device__ __align__(16) int    g_bbase [SCAN_B];
__device__ __align__(16) float  g_dinv  [N_NODES];
__device__ __align__(16) int    g_ecol  [N_EDGES];
__device__ __align__(16) float  g_u0    [(size_t)N_NODES * OUT_CH]; // raw xW (fp32)
__device__ __align__(16) __half g_h0    [(size_t)N_NODES * OUT_CH]; // h0s = dinv*(xW)
__device__ __align__(16) __half g_h1    [(size_t)N_NODES * OUT_CH]; // h1s
__device__ __align__(16) __nv_bfloat16 g_Wth[OUT_CH][IN_CH];
__device__ __align__(16) __nv_bfloat16 g_Wtl[OUT_CH][IN_CH];

// ---------------- zero counts ----------------
__global__ void zero_cnt_kernel() {
    int i = blockIdx.x * blockDim.x + threadIdx.x;
    if (i < N_NODES) g_cnt[i] = 0;
}

// warp-parallel dtype probe: 32 lanes x 8 independent loads
__global__ void detect_kernel(const int* __restrict__ buf) {
    int lane = threadIdx.x;
    int any = 0;
    #pragma unroll
    for (int j = 0; j < 8; j++) {
        if (buf[2 * (lane * 8 + j) + 1] != 0) any = 1;
    }
    any = __any_sync(0xFFFFFFFFu, any);
    if (lane == 0) g_is64 = any ? 0 : 1;
}

// load TWO consecutive edges (2e, 2e+1) with vector index loads
__device__ __forceinline__ void load_edge2(const void* buf, int e2,
                                           int& r0, int& c0, int& r1, int& c1) {
    if (g_is64) {
        const longlong2* pr = (const longlong2*)((const long long*)buf) + e2;
        const longlong2* pc = (const longlong2*)((const long long*)buf + N_EDGES) + e2;
        longlong2 rr = *pr;
        longlong2 cc = *pc;
        r0 = (int)rr.x; r1 = (int)rr.y;
        c0 = (int)cc.x; c1 = (int)cc.y;
    } else {
        const int2* pr = (const int2*)((const int*)buf) + e2;
        const int2* pc = (const int2*)((const int*)buf + N_EDGES) + e2;
        int2 rr = *pr;
        int2 cc = *pc;
        r0 = rr.x; r1 = rr.y;
        c0 = cc.x; c1 = cc.y;
    }
}

__global__ void hist_kernel(const void* __restrict__ buf) {
    int e2 = blockIdx.x * blockDim.x + threadIdx.x;   // edge-pair index
    if (e2 >= N_EDGES / 2) return;
    int r0, c0, r1, c1;
    load_edge2(buf, e2, r0, c0, r1, c1);
    if ((unsigned)r0 < N_NODES && (unsigned)c0 < N_NODES && r0 != c0)
        atomicAdd(&g_cnt[r0], 1);
    if ((unsigned)r1 < N_NODES && (unsigned)c1 < N_NODES && r1 != c1)
        atomicAdd(&g_cnt[r1], 1);
}

// ---------------- 3-phase scan: g_cnt -> g_rowptr (+ dinv, cursor) ----------
__global__ __launch_bounds__(1024) void scanA_kernel() {
    __shared__ int wsum[32];
    int b = blockIdx.x, t = threadIdx.x;
    int i = b * 1024 + t;
    int v = (i < N_NODES) ? g_cnt[i] : 0;
    int lane = t & 31, wid = t >> 5;
    int s = v;
    #pragma unroll
    for (int off = 16; off > 0; off >>= 1) s += __shfl_xor_sync(~0u, s, off);
    if (lane == 0) wsum[wid] = s;
    __syncthreads();
    if (wid == 0) {
        int w = wsum[lane];
        #pragma unroll
        for (int off = 16; off > 0; off >>= 1) w += __shfl_xor_sync(~0u, w, off);
        if (lane == 0) g_bsum[b] = w;
    }
}

__global__ void scanB_kernel() {
    int lane = threadIdx.x;                 // 32 threads
    int v[4];
    int local = 0;
    #pragma unroll
    for (int j = 0; j < 4; j++) {
        int i = lane * 4 + j;
        v[j] = (i < SCAN_B) ? g_bsum[i] : 0;
        local += v[j];
    }
    int incl = local;
    #pragma unroll
    for (int off = 1; off < 32; off <<= 1) {
        int n = __shfl_up_sync(~0u, incl, off);
        if (lane >= off) incl += n;
    }
    int run = incl - local;
    #pragma unroll
    for (int j = 0; j < 4; j++) {
        int i = lane * 4 + j;
        if (i < SCAN_B) g_bbase[i] = run;
        run += v[j];
    }
    if (lane == 31) g_rowptr[N_NODES] = incl;
}

__global__ __launch_bounds__(1024) void scanC_kernel() {
    __shared__ int wsum[32];
    int b = blockIdx.x, t = threadIdx.x;
    int i = b * 1024 + t;
    int v = (i < N_NODES) ? g_cnt[i] : 0;
    int lane = t & 31, wid = t >> 5;
    int incl = v;
    #pragma unroll
    for (int off = 1; off < 32; off <<= 1) {
        int n = __shfl_up_sync(~0u, incl, off);
        if (lane >= off) incl += n;
    }
    if (lane == 31) wsum[wid] = incl;
    __syncthreads();
    if (wid == 0) {
        int s = wsum[lane];
        #pragma unroll
        for (int off = 1; off < 32; off <<= 1) {
            int n = __shfl_up_sync(~0u, s, off);
            if (lane >= off) s += n;
        }
        wsum[lane] = s;
    }
    __syncthreads();
    if (i < N_NODES) {
        int excl = incl - v + (wid > 0 ? wsum[wid - 1] : 0) + g_bbase[b];
        g_rowptr[i] = excl;
        g_cur[i]    = excl;                       // scatter cursor
        g_dinv[i]   = rsqrtf((float)v + 1.0f);
    }
}

// scatter via cursor: one atomic, no rowptr load
__global__ void scatter_kernel(const void* __restrict__ buf) {
    int e2 = blockIdx.x * blockDim.x + threadIdx.x;
    if (e2 >= N_EDGES / 2) return;
    int r0, c0, r1, c1;
    load_edge2(buf, e2, r0, c0, r1, c1);
    if ((unsigned)r0 < N_NODES && (unsigned)c0 < N_NODES && r0 != c0) {
        int pos = atomicAdd(&g_cur[r0], 1);
        g_ecol[pos] = c0;
    }
    if ((unsigned)r1 < N_NODES && (unsigned)c1 < N_NODES && r1 != c1) {
        int pos = atomicAdd(&g_cur[r1], 1);
        g_ecol[pos] = c1;
    }
}

// ---------------- W split/transpose ----------------
__global__ void wsplit_kernel(const float* __restrict__ W) {
    int t = blockIdx.x * blockDim.x + threadIdx.x;
    if (t >= IN_CH * OUT_CH) return;
    int n = t / IN_CH;
    int k = t % IN_CH;
    float v = W[(size_t)k * OUT_CH + n];
    __nv_bfloat16 hi = __float2bfloat16(v);
    __nv_bfloat16 lo = __float2bfloat16(v - __bfloat162float(hi));
    g_Wth[n][k] = hi;
    g_Wtl[n][k] = lo;
}

// ---------------- GEMM: g_u0 = x @ W (raw fp32) -----------------------------
#define GBM 128
#define GBK 32
#define SAS 17

__device__ __forceinline__ uint32_t pack_bf16(__nv_bfloat16 a, __nv_bfloat16 b) {
    return (uint32_t)__bfloat16_as_ushort(a) | ((uint32_t)__bfloat16_as_ushort(b) << 16);
}

__device__ __forceinline__ void mma16816(float c[4], const uint32_t a[4],
                                         const uint32_t b[2]) {
    asm volatile(
        "mma.sync.aligned.m16n8k16.row.col.f32.bf16.bf16.f32 "
        "{%0,%1,%2,%3}, {%4,%5,%6,%7}, {%8,%9}, {%0,%1,%2,%3};"
        : "+f"(c[0]), "+f"(c[1]), "+f"(c[2]), "+f"(c[3])
        : "r"(a[0]), "r"(a[1]), "r"(a[2]), "r"(a[3]), "r"(b[0]), "r"(b[1]));
}

__global__ __launch_bounds__(256, 2) void gemm_mma_kernel(const float* __restrict__ x) {
    __shared__ uint32_t sAh[GBM][SAS];
    __shared__ uint32_t sAl[GBM][SAS];
    __shared__ uint32_t sBh[OUT_CH][SAS];
    __shared__ uint32_t sBl[OUT_CH][SAS];

    int tid  = threadIdx.x;
    int wid  = tid >> 5, lane = tid & 31;
    int wm   = wid & 3,  wn   = wid >> 2;
    int grp  = lane >> 2, t4  = lane & 3;
    int m0   = blockIdx.x * GBM;

    float c[2][4][4];
    #pragma unroll
    for (int i = 0; i < 2; i++)
        #pragma unroll
        for (int j = 0; j < 4; j++)
            #pragma unroll
            for (int k = 0; k < 4; k++) c[i][j][k] = 0.0f;

    float4   xr[4];
    uint32_t wh[4], wl[4];

    #pragma unroll
    for (int i = 0; i < 4; i++) {
        int idx = tid + i * 256;
        int row = idx >> 3, f4 = idx & 7;
        xr[i] = make_float4(0.f, 0.f, 0.f, 0.f);
        if (m0 + row < N_NODES)
            xr[i] = *(const float4*)(x + (size_t)(m0 + row) * IN_CH + f4 * 4);
        int n = idx >> 4, kp = idx & 15;
        wh[i] = ((const uint32_t*)&g_Wth[n][0])[kp];
        wl[i] = ((const uint32_t*)&g_Wtl[n][0])[kp];
    }

    for (int k0 = 0; k0 < IN_CH; k0 += GBK) {
        #pragma unroll
        for (int i = 0; i < 4; i++) {
            int idx = tid + i * 256;
            int row = idx >> 3, f4 = idx & 7;
            float4 v = xr[i];
            __nv_bfloat16 hx = __float2bfloat16(v.x);
            __nv_bfloat16 hy = __float2bfloat16(v.y);
            __nv_bfloat16 hz = __float2bfloat16(v.z);
            __nv_bfloat16 hw = __float2bfloat16(v.w);
            sAh[row][f4 * 2]     = pack_bf16(hx, hy);
            sAh[row][f4 * 2 + 1] = pack_bf16(hz, hw);
            __nv_bfloat16 lx = __float2bfloat16(v.x - __bfloat162float(hx));
            __nv_bfloat16 ly = __float2bfloat16(v.y - __bfloat162float(hy));
            __nv_bfloat16 lz = __float2bfloat16(v.z - __bfloat162float(hz));
            __nv_bfloat16 lw = __float2bfloat16(v.w - __bfloat162float(hw));
            sAl[row][f4 * 2]     = pack_bf16(lx, ly);
            sAl[row][f4 * 2 + 1] = pack_bf16(lz, lw);
            int n = idx >> 4, kp = idx & 15;
            sBh[n][kp] = wh[i];
            sBl[n][kp] = wl[i];
        }
        __syncthreads();

        int kn = k0 + GBK;
        if (kn < IN_CH) {
            #pragma unroll
            for (int i = 0; i < 4; i++) {
                int idx = tid + i * 256;
                int row = idx >> 3, f4 = idx & 7;
                xr[i] = make_float4(0.f, 0.f, 0.f, 0.f);
                if (m0 + row < N_NODES)
                    xr[i] = *(const float4*)(x + (size_t)(m0 + row) * IN_CH + kn + f4 * 4);
                int n = idx >> 4, kp = idx & 15;
                wh[i] = ((const uint32_t*)&g_Wth[n][kn])[kp];
                wl[i] = ((const uint32_t*)&g_Wtl[n][kn])[kp];
            }
        }

        #pragma unroll
        for (int kt = 0; kt < 2; kt++) {
            int kp0 = kt * 8;
            uint32_t ah[2][4], al[2][4];
            #pragma unroll
            for (int mt = 0; mt < 2; mt++) {
                int r = wm * 32 + mt * 16 + grp;
                ah[mt][0] = sAh[r][kp0 + t4];
                ah[mt][1] = sAh[r + 8][kp0 + t4];
                ah[mt][2] = sAh[r][kp0 + t4 + 4];
                ah[mt][3] = sAh[r + 8][kp0 + t4 + 4];
                al[mt][0] = sAl[r][kp0 + t4];
                al[mt][1] = sAl[r + 8][kp0 + t4];
                al[mt][2] = sAl[r][kp0 + t4 + 4];
                al[mt][3] = sAl[r + 8][kp0 + t4 + 4];
            }
            uint32_t bh[4][2], bl[4][2];
            #pragma unroll
            for (int nt = 0; nt < 4; nt++) {
                int n = wn * 32 + nt * 8 + grp;
                bh[nt][0] = sBh[n][kp0 + t4];
                bh[nt][1] = sBh[n][kp0 + t4 + 4];
                bl[nt][0] = sBl[n][kp0 + t4];
                bl[nt][1] = sBl[n][kp0 + t4 + 4];
            }
            #pragma unroll
            for (int mt = 0; mt < 2; mt++)
                #pragma unroll
                for (int nt = 0; nt < 4; nt++) {
                    mma16816(c[mt][nt], ah[mt], bh[nt]);
                    mma16816(c[mt][nt], ah[mt], bl[nt]);
                    mma16816(c[mt][nt], al[mt], bh[nt]);
                }
        }
        __syncthreads();
    }

    #pragma unroll
    for (int mt = 0; mt < 2; mt++) {
        int r0 = m0 + wm * 32 + mt * 16 + grp;
        int r1 = r0 + 8;
        #pragma unroll
        for (int nt = 0; nt < 4; nt++) {
            int col = wn * 32 + nt * 8 + t4 * 2;
            if (r0 < N_NODES) {
                float2 v = make_float2(c[mt][nt][0], c[mt][nt][1]);
                *(float2*)(g_u0 + (size_t)r0 * OUT_CH + col) = v;
            }
            if (r1 < N_NODES) {
                float2 v = make_float2(c[mt][nt][2], c[mt][nt][3]);
                *(float2*)(g_u0 + (size_t)r1 * OUT_CH + col) = v;
            }
        }
    }
}

// h0 = fp16( dinv[node] * u0 )   (needs GEMM + scanC; runs ∥ scatter)
__global__ void scale_h0_kernel() {
    int idx = blockIdx.x * blockDim.x + threadIdx.x;   // 4-elem chunk index
    const int total = N_NODES * OUT_CH / 4;
    if (idx >= total) return;
    int node = idx >> 4;
    float s = g_dinv[node];
    float4 v = *(const float4*)(g_u0 + (size_t)idx * 4);
    __half2 h0 = __floats2half2_rn(v.x * s, v.y * s);
    __half2 h1 = __floats2half2_rn(v.z * s, v.w * s);
    uint2 u;
    u.x = *(uint32_t*)&h0;
    u.y = *(uint32_t*)&h1;
    *(uint2*)(g_h0 + (size_t)idx * 4) = u;
}

// ---------------- gather: fp16 rows, 8 lanes/edge (4 edges/warp-instr),
// 2-slot pipelined ecol prefetch (8 edges in flight per warp) — R13 proven --
// MODE 0: hin=g_h0, hout=g_h1 (fp16), scale=d^2
// MODE 1: hin=g_h1, hout=outp (fp32), scale=d
template <int MODE>
__global__ __launch_bounds__(256) void gather_kernel(float* __restrict__ outp) {
    int node = (int)((blockIdx.x * blockDim.x + threadIdx.x) >> 5);
    if (node >= N_NODES) return;
    int lane = threadIdx.x & 31;

    const __half* __restrict__ hin = (MODE == 0) ? g_h0 : g_h1;

    int start = g_rowptr[node];
    int end   = g_rowptr[node + 1];
    int sub  = lane & 7;                // 8-lane group position
    int ch   = sub << 3;                // half offset: 0..56 (uint4 = 8 halves)
    int eoff = lane >> 3;               // 0..3: edge slot within warp

    float acc[8];
    #pragma unroll
    for (int i = 0; i < 8; i++) acc[i] = 0.0f;

    int e0 = start + eoff;
    int c[2];
    #pragma unroll
    for (int j = 0; j < 2; j++) {
        int e = e0 + j * 4;
        c[j] = (e < end) ? g_ecol[e] : -1;
    }
    for (int base = e0; base < end; base += 8) {
        int cn[2];
        #pragma unroll
        for (int j = 0; j < 2; j++) {
            int e = base + 8 + j * 4;
            cn[j] = (e < end) ? g_ecol[e] : -1;
        }
        #pragma unroll
        for (int j = 0; j < 2; j++) {
            if (c[j] >= 0) {
                uint4 u = *(const uint4*)(hin + (size_t)c[j] * OUT_CH + ch);
                float2 f;
                f = __half22float2(*(__half2*)&u.x); acc[0] += f.x; acc[1] += f.y;
                f = __half22float2(*(__half2*)&u.y); acc[2] += f.x; acc[3] += f.y;
                f = __half22float2(*(__half2*)&u.z); acc[4] += f.x; acc[5] += f.y;
                f = __half22float2(*(__half2*)&u.w); acc[6] += f.x; acc[7] += f.y;
            }
            c[j] = cn[j];
        }
    }

    // combine the 4 edge-slots (xor 8, xor 16)
    #pragma unroll
    for (int i = 0; i < 8; i++) {
        acc[i] += __shfl_xor_sync(0xFFFFFFFFu, acc[i], 8);
        acc[i] += __shfl_xor_sync(0xFFFFFFFFu, acc[i], 16);
    }

    if (lane < 8) {
        float d = g_dinv[node];
        float s = (MODE == 0) ? d * d : d;
        uint4 su = *(const uint4*)(hin + (size_t)node * OUT_CH + ch);
        float2 f;
        f = __half22float2(*(__half2*)&su.x); acc[0] += f.x; acc[1] += f.y;
        f = __half22float2(*(__half2*)&su.y); acc[2] += f.x; acc[3] += f.y;
        f = __half22float2(*(__half2*)&su.z); acc[4] += f.x; acc[5] += f.y;
        f = __half22float2(*(__half2*)&su.w); acc[6] += f.x; acc[7] += f.y;
        #pragma unroll
        for (int i = 0; i < 8; i++) acc[i] *= s;

        if (MODE == 0) {
            __half2 o[4];
            #pragma unroll
            for (int j = 0; j < 4; j++)
                o[j] = __floats2half2_rn(acc[2 * j], acc[2 * j + 1]);
            *(uint4*)(g_h1 + (size_t)node * OUT_CH + ch) = *(uint4*)o;
        } else {
            float* dst = outp + (size_t)node * OUT_CH + ch;
            *(float4*)(dst)     = make_float4(acc[0], acc[1], acc[2], acc[3]);
            *(float4*)(dst + 4) = make_float4(acc[4], acc[5], acc[6], acc[7]);
        }
    }
}

extern "C" void kernel_launch(void* const* d_in, const int* in_sizes, int n_in,
                              void* d_out, int out_size) {
    const void*  edge_index = d_in[0];               // [2, N_EDGES] int32 or int64
    const float* x          = (const float*)d_in[1]; // [N_NODES, 512]
    const float* W          = (const float*)d_in[2]; // [512, 64]
    float*       out        = (float*)d_out;         // [N_NODES, 64]

    cudaStream_t s1;
    cudaEvent_t  evRoot, evScan, evScale;
    cudaStreamCreateWithFlags(&s1, cudaStreamNonBlocking);
    cudaEventCreateWithFlags(&evRoot,  cudaEventDisableTiming);
    cudaEventCreateWithFlags(&evScan,  cudaEventDisableTiming);
    cudaEventCreateWithFlags(&evScale, cudaEventDisableTiming);

    cudaEventRecord(evRoot, 0);
    cudaStreamWaitEvent(s1, evRoot, 0);

    // s1: weight split + raw GEMM (needs only x, W)
    wsplit_kernel<<<(IN_CH * OUT_CH + 255) / 256, 256, 0, s1>>>(W);
    gemm_mma_kernel<<<(N_NODES + GBM - 1) / GBM, 256, 0, s1>>>(x);

    // s0: CSR build chain (2 edges per thread, warp-parallel probe)
    zero_cnt_kernel<<<(N_NODES + 255) / 256, 256>>>();
    detect_kernel<<<1, 32>>>((const int*)edge_index);
    hist_kernel<<<(N_EDGES / 2 + 255) / 256, 256>>>(edge_index);
    scanA_kernel<<<SCAN_B, 1024>>>();
    scanB_kernel<<<1, 32>>>();
    scanC_kernel<<<SCAN_B, 1024>>>();
    cudaEventRecord(evScan, 0);

    // s1: scale_h0 (GEMM done on s1; scanC via event) — overlaps scatter
    cudaStreamWaitEvent(s1, evScan, 0);
    const int vec_total = N_NODES * OUT_CH / 4;
    scale_h0_kernel<<<(vec_total + 255) / 256, 256, 0, s1>>>();
    cudaEventRecord(evScale, s1);

    // s0: scatter ∥ scale_h0, then join and run the two hops
    scatter_kernel<<<(N_EDGES / 2 + 255) / 256, 256>>>(edge_index);
    cudaStreamWaitEvent(0, evScale, 0);

    const int blocks = (N_NODES * 32 + 255) / 256;
    gather_kernel<0><<<blocks, 256>>>(nullptr);
    gather_kernel<1><<<blocks, 256>>>(out);
}

// round 17
// speedup vs baseline: 1.0354x; 1.0090x over previous
#include <cuda_runtime.h>
#include <cuda_fp16.h>
#include <cuda_bf16.h>
#include <cstdint>

#define N_NODES 100000
#define N_EDGES 3200000
#define IN_CH   512
#define OUT_CH  64
#define SCAN_B  98          // ceil(N_NODES / 1024)

// ---- scratch: __device__ globals only ----
__device__ int g_is64;
__device__ __align__(16) int    g_cnt   [N_NODES];
__device__ __align__(16) int    g_cur   [N_NODES];
__device__ __align__(16) int    g_rowptr[N_NODES + 1];
__device__ __align__(16) int    g_bsum  [SCAN_B];
__device__ __align__(16) int    g_bbase [SCAN_B];
__device__ __align__(16) float  g_dinv  [N_NODES];
__device__ __align__(16) int    g_ecol  [N_EDGES];
__device__ __align__(16) float  g_u0    [(size_t)N_NODES * OUT_CH]; // raw xW (fp32)
__device__ __align__(16) __half g_h0    [(size_t)N_NODES * OUT_CH]; // h0s = dinv*(xW)
__device__ __align__(16) __half g_h1    [(size_t)N_NODES * OUT_CH]; // h1s
__device__ __align__(16) __nv_bfloat16 g_Wth[OUT_CH][IN_CH];
__device__ __align__(16) __nv_bfloat16 g_Wtl[OUT_CH][IN_CH];

// ---------------- zero counts + warp-parallel dtype probe (one launch) ------
__global__ void zero_detect_kernel(const int* __restrict__ buf) {
    int i = blockIdx.x * blockDim.x + threadIdx.x;
    if (i < N_NODES) g_cnt[i] = 0;
    if (blockIdx.x == 0 && threadIdx.x < 32) {
        int lane = threadIdx.x;
        int any = 0;
        #pragma unroll
        for (int j = 0; j < 8; j++) {
            if (buf[2 * (lane * 8 + j) + 1] != 0) any = 1;
        }
        any = __any_sync(0xFFFFFFFFu, any);
        if (lane == 0) g_is64 = any ? 0 : 1;
    }
}

// load TWO consecutive edges (2e, 2e+1) with vector index loads
__device__ __forceinline__ void load_edge2(const void* buf, int e2,
                                           int& r0, int& c0, int& r1, int& c1) {
    if (g_is64) {
        const longlong2* pr = (const longlong2*)((const long long*)buf) + e2;
        const longlong2* pc = (const longlong2*)((const long long*)buf + N_EDGES) + e2;
        longlong2 rr = *pr;
        longlong2 cc = *pc;
        r0 = (int)rr.x; r1 = (int)rr.y;
        c0 = (int)cc.x; c1 = (int)cc.y;
    } else {
        const int2* pr = (const int2*)((const int*)buf) + e2;
        const int2* pc = (const int2*)((const int*)buf + N_EDGES) + e2;
        int2 rr = *pr;
        int2 cc = *pc;
        r0 = rr.x; r1 = rr.y;
        c0 = cc.x; c1 = cc.y;
    }
}

__global__ void hist_kernel(const void* __restrict__ buf) {
    int e2 = blockIdx.x * blockDim.x + threadIdx.x;   // edge-pair index
    if (e2 >= N_EDGES / 2) return;
    int r0, c0, r1, c1;
    load_edge2(buf, e2, r0, c0, r1, c1);
    if ((unsigned)r0 < N_NODES && (unsigned)c0 < N_NODES && r0 != c0)
        atomicAdd(&g_cnt[r0], 1);
    if ((unsigned)r1 < N_NODES && (unsigned)c1 < N_NODES && r1 != c1)
        atomicAdd(&g_cnt[r1], 1);
}

// ---------------- 3-phase scan: g_cnt -> g_rowptr (+ dinv, cursor) ----------
__global__ __launch_bounds__(1024) void scanA_kernel() {
    __shared__ int wsum[32];
    int b = blockIdx.x, t = threadIdx.x;
    int i = b * 1024 + t;
    int v = (i < N_NODES) ? g_cnt[i] : 0;
    int lane = t & 31, wid = t >> 5;
    int s = v;
    #pragma unroll
    for (int off = 16; off > 0; off >>= 1) s += __shfl_xor_sync(~0u, s, off);
    if (lane == 0) wsum[wid] = s;
    __syncthreads();
    if (wid == 0) {
        int w = wsum[lane];
        #pragma unroll
        for (int off = 16; off > 0; off >>= 1) w += __shfl_xor_sync(~0u, w, off);
        if (lane == 0) g_bsum[b] = w;
    }
}

__global__ void scanB_kernel() {
    int lane = threadIdx.x;                 // 32 threads
    int v[4];
    int local = 0;
    #pragma unroll
    for (int j = 0; j < 4; j++) {
        int i = lane * 4 + j;
        v[j] = (i < SCAN_B) ? g_bsum[i] : 0;
        local += v[j];
    }
    int incl = local;
    #pragma unroll
    for (int off = 1; off < 32; off <<= 1) {
        int n = __shfl_up_sync(~0u, incl, off);
        if (lane >= off) incl += n;
    }
    int run = incl - local;
    #pragma unroll
    for (int j = 0; j < 4; j++) {
        int i = lane * 4 + j;
        if (i < SCAN_B) g_bbase[i] = run;
        run += v[j];
    }
    if (lane == 31) g_rowptr[N_NODES] = incl;
}

__global__ __launch_bounds__(1024) void scanC_kernel() {
    __shared__ int wsum[32];
    int b = blockIdx.x, t = threadIdx.x;
    int i = b * 1024 + t;
    int v = (i < N_NODES) ? g_cnt[i] : 0;
    int lane = t & 31, wid = t >> 5;
    int incl = v;
    #pragma unroll
    for (int off = 1; off < 32; off <<= 1) {
        int n = __shfl_up_sync(~0u, incl, off);
        if (lane >= off) incl += n;
    }
    if (lane == 31) wsum[wid] = incl;
    __syncthreads();
    if (wid == 0) {
        int s = wsum[lane];
        #pragma unroll
        for (int off = 1; off < 32; off <<= 1) {
            int n = __shfl_up_sync(~0u, s, off);
            if (lane >= off) s += n;
        }
        wsum[lane] = s;
    }
    __syncthreads();
    if (i < N_NODES) {
        int excl = incl - v + (wid > 0 ? wsum[wid - 1] : 0) + g_bbase[b];
        g_rowptr[i] = excl;
        g_cur[i]    = excl;                       // scatter cursor
        g_dinv[i]   = rsqrtf((float)v + 1.0f);
    }
}

// scatter via cursor: one atomic, no rowptr load
__global__ void scatter_kernel(const void* __restrict__ buf) {
    int e2 = blockIdx.x * blockDim.x + threadIdx.x;
    if (e2 >= N_EDGES / 2) return;
    int r0, c0, r1, c1;
    load_edge2(buf, e2, r0, c0, r1, c1);
    if ((unsigned)r0 < N_NODES && (unsigned)c0 < N_NODES && r0 != c0) {
        int pos = atomicAdd(&g_cur[r0], 1);
        g_ecol[pos] = c0;
    }
    if ((unsigned)r1 < N_NODES && (unsigned)c1 < N_NODES && r1 != c1) {
        int pos = atomicAdd(&g_cur[r1], 1);
        g_ecol[pos] = c1;
    }
}

// ---------------- W split/transpose ----------------
__global__ void wsplit_kernel(const float* __restrict__ W) {
    int t = blockIdx.x * blockDim.x + threadIdx.x;
    if (t >= IN_CH * OUT_CH) return;
    int n = t / IN_CH;
    int k = t % IN_CH;
    float v = W[(size_t)k * OUT_CH + n];
    __nv_bfloat16 hi = __float2bfloat16(v);
    __nv_bfloat16 lo = __float2bfloat16(v - __bfloat162float(hi));
    g_Wth[n][k] = hi;
    g_Wtl[n][k] = lo;
}

// ---------------- GEMM: g_u0 = x @ W (raw fp32), packed bf16x2 cvt ----------
#define GBM 128
#define GBK 32
#define SAS 17

// packed convert: word = { lo16 = bf16(a), hi16 = bf16(b) }
__device__ __forceinline__ uint32_t cvt_bf16x2(float a, float b) {
    uint32_t r;
    asm("cvt.rn.bf16x2.f32 %0, %1, %2;" : "=r"(r) : "f"(b), "f"(a));
    return r;
}

__device__ __forceinline__ void mma16816(float c[4], const uint32_t a[4],
                                         const uint32_t b[2]) {
    asm volatile(
        "mma.sync.aligned.m16n8k16.row.col.f32.bf16.bf16.f32 "
        "{%0,%1,%2,%3}, {%4,%5,%6,%7}, {%8,%9}, {%0,%1,%2,%3};"
        : "+f"(c[0]), "+f"(c[1]), "+f"(c[2]), "+f"(c[3])
        : "r"(a[0]), "r"(a[1]), "r"(a[2]), "r"(a[3]), "r"(b[0]), "r"(b[1]));
}

__global__ __launch_bounds__(256, 2) void gemm_mma_kernel(const float* __restrict__ x) {
    __shared__ uint32_t sAh[GBM][SAS];
    __shared__ uint32_t sAl[GBM][SAS];
    __shared__ uint32_t sBh[OUT_CH][SAS];
    __shared__ uint32_t sBl[OUT_CH][SAS];

    int tid  = threadIdx.x;
    int wid  = tid >> 5, lane = tid & 31;
    int wm   = wid & 3,  wn   = wid >> 2;
    int grp  = lane >> 2, t4  = lane & 3;
    int m0   = blockIdx.x * GBM;

    float c[2][4][4];
    #pragma unroll
    for (int i = 0; i < 2; i++)
        #pragma unroll
        for (int j = 0; j < 4; j++)
            #pragma unroll
            for (int k = 0; k < 4; k++) c[i][j][k] = 0.0f;

    float4   xr[4];
    uint32_t wh[4], wl[4];

    #pragma unroll
    for (int i = 0; i < 4; i++) {
        int idx = tid + i * 256;
        int row = idx >> 3, f4 = idx & 7;
        xr[i] = make_float4(0.f, 0.f, 0.f, 0.f);
        if (m0 + row < N_NODES)
            xr[i] = *(const float4*)(x + (size_t)(m0 + row) * IN_CH + f4 * 4);
        int n = idx >> 4, kp = idx & 15;
        wh[i] = ((const uint32_t*)&g_Wth[n][0])[kp];
        wl[i] = ((const uint32_t*)&g_Wtl[n][0])[kp];
    }

    for (int k0 = 0; k0 < IN_CH; k0 += GBK) {
        #pragma unroll
        for (int i = 0; i < 4; i++) {
            int idx = tid + i * 256;
            int row = idx >> 3, f4 = idx & 7;
            float4 v = xr[i];
            // packed hi conversion (1 instr per pair)
            uint32_t h0 = cvt_bf16x2(v.x, v.y);
            uint32_t h1 = cvt_bf16x2(v.z, v.w);
            sAh[row][f4 * 2]     = h0;
            sAh[row][f4 * 2 + 1] = h1;
            // residuals: unpack hi back to fp32 via shift/mask (1 ALU each)
            float rx = v.x - __uint_as_float(h0 << 16);
            float ry = v.y - __uint_as_float(h0 & 0xFFFF0000u);
            float rz = v.z - __uint_as_float(h1 << 16);
            float rw = v.w - __uint_as_float(h1 & 0xFFFF0000u);
            sAl[row][f4 * 2]     = cvt_bf16x2(rx, ry);
            sAl[row][f4 * 2 + 1] = cvt_bf16x2(rz, rw);
            int n = idx >> 4, kp = idx & 15;
            sBh[n][kp] = wh[i];
            sBl[n][kp] = wl[i];
        }
        __syncthreads();

        int kn = k0 + GBK;
        if (kn < IN_CH) {
            #pragma unroll
            for (int i = 0; i < 4; i++) {
                int idx = tid + i * 256;
                int row = idx >> 3, f4 = idx & 7;
                xr[i] = make_float4(0.f, 0.f, 0.f, 0.f);
                if (m0 + row < N_NODES)
                    xr[i] = *(const float4*)(x + (size_t)(m0 + row) * IN_CH + kn + f4 * 4);
                int n = idx >> 4, kp = idx & 15;
                wh[i] = ((const uint32_t*)&g_Wth[n][kn])[kp];
                wl[i] = ((const uint32_t*)&g_Wtl[n][kn])[kp];
            }
        }

        #pragma unroll
        for (int kt = 0; kt < 2; kt++) {
            int kp0 = kt * 8;
            uint32_t ah[2][4], al[2][4];
            #pragma unroll
            for (int mt = 0; mt < 2; mt++) {
                int r = wm * 32 + mt * 16 + grp;
                ah[mt][0] = sAh[r][kp0 + t4];
                ah[mt][1] = sAh[r + 8][kp0 + t4];
                ah[mt][2] = sAh[r][kp0 + t4 + 4];
                ah[mt][3] = sAh[r + 8][kp0 + t4 + 4];
                al[mt][0] = sAl[r][kp0 + t4];
                al[mt][1] = sAl[r + 8][kp0 + t4];
                al[mt][2] = sAl[r][kp0 + t4 + 4];
                al[mt][3] = sAl[r + 8][kp0 + t4 + 4];
            }
            uint32_t bh[4][2], bl[4][2];
            #pragma unroll
            for (int nt = 0; nt < 4; nt++) {
                int n = wn * 32 + nt * 8 + grp;
                bh[nt][0] = sBh[n][kp0 + t4];
                bh[nt][1] = sBh[n][kp0 + t4 + 4];
                bl[nt][0] = sBl[n][kp0 + t4];
                bl[nt][1] = sBl[n][kp0 + t4 + 4];
            }
            #pragma unroll
            for (int mt = 0; mt < 2; mt++)
                #pragma unroll
                for (int nt = 0; nt < 4; nt++) {
                    mma16816(c[mt][nt], ah[mt], bh[nt]);
                    mma16816(c[mt][nt], ah[mt], bl[nt]);
                    mma16816(c[mt][nt], al[mt], bh[nt]);
                }
        }
        __syncthreads();
    }

    #pragma unroll
    for (int mt = 0; mt < 2; mt++) {
        int r0 = m0 + wm * 32 + mt * 16 + grp;
        int r1 = r0 + 8;
        #pragma unroll
        for (int nt = 0; nt < 4; nt++) {
            int col = wn * 32 + nt * 8 + t4 * 2;
            if (r0 < N_NODES) {
                float2 v = make_float2(c[mt][nt][0], c[mt][nt][1]);
                *(float2*)(g_u0 + (size_t)r0 * OUT_CH + col) = v;
            }
            if (r1 < N_NODES) {
                float2 v = make_float2(c[mt][nt][2], c[mt][nt][3]);
                *(float2*)(g_u0 + (size_t)r1 * OUT_CH + col) = v;
            }
        }
    }
}

// h0 = fp16( dinv[node] * u0 )   (needs GEMM + scanC; runs ∥ scatter)
__global__ void scale_h0_kernel() {
    int idx = blockIdx.x * blockDim.x + threadIdx.x;   // 4-elem chunk index
    const int total = N_NODES * OUT_CH / 4;
    if (idx >= total) return;
    int node = idx >> 4;
    float s = g_dinv[node];
    float4 v = *(const float4*)(g_u0 + (size_t)idx * 4);
    __half2 h0 = __floats2half2_rn(v.x * s, v.y * s);
    __half2 h1 = __floats2half2_rn(v.z * s, v.w * s);
    uint2 u;
    u.x = *(uint32_t*)&h0;
    u.y = *(uint32_t*)&h1;
    *(uint2*)(g_h0 + (size_t)idx * 4) = u;
}

// ---------------- gather: fp16 rows, 8 lanes/edge (4 edges/warp-instr),
// 2-slot pipelined ecol prefetch (8 edges in flight per warp) — R13 proven --
// MODE 0: hin=g_h0, hout=g_h1 (fp16), scale=d^2
// MODE 1: hin=g_h1, hout=outp (fp32), scale=d
template <int MODE>
__global__ __launch_bounds__(256) void gather_kernel(float* __restrict__ outp) {
    int node = (int)((blockIdx.x * blockDim.x + threadIdx.x) >> 5);
    if (node >= N_NODES) return;
    int lane = threadIdx.x & 31;

    const __half* __restrict__ hin = (MODE == 0) ? g_h0 : g_h1;

    int start = g_rowptr[node];
    int end   = g_rowptr[node + 1];
    int sub  = lane & 7;                // 8-lane group position
    int ch   = sub << 3;                // half offset: 0..56 (uint4 = 8 halves)
    int eoff = lane >> 3;               // 0..3: edge slot within warp

    float acc[8];
    #pragma unroll
    for (int i = 0; i < 8; i++) acc[i] = 0.0f;

    int e0 = start + eoff;
    int c[2];
    #pragma unroll
    for (int j = 0; j < 2; j++) {
        int e = e0 + j * 4;
        c[j] = (e < end) ? g_ecol[e] : -1;
    }
    for (int base = e0; base < end; base += 8) {
        int cn[2];
        #pragma unroll
        for (int j = 0; j < 2; j++) {
            int e = base + 8 + j * 4;
            cn[j] = (e < end) ? g_ecol[e] : -1;
        }
        #pragma unroll
        for (int j = 0; j < 2; j++) {
            if (c[j] >= 0) {
                uint4 u = *(const uint4*)(hin + (size_t)c[j] * OUT_CH + ch);
                float2 f;
                f = __half22float2(*(__half2*)&u.x); acc[0] += f.x; acc[1] += f.y;
                f = __half22float2(*(__half2*)&u.y); acc[2] += f.x; acc[3] += f.y;
                f = __half22float2(*(__half2*)&u.z); acc[4] += f.x; acc[5] += f.y;
                f = __half22float2(*(__half2*)&u.w); acc[6] += f.x; acc[7] += f.y;
            }
            c[j] = cn[j];
        }
    }

    // combine the 4 edge-slots (xor 8, xor 16)
    #pragma unroll
    for (int i = 0; i < 8; i++) {
        acc[i] += __shfl_xor_sync(0xFFFFFFFFu, acc[i], 8);
        acc[i] += __shfl_xor_sync(0xFFFFFFFFu, acc[i], 16);
    }

    if (lane < 8) {
        float d = g_dinv[node];
        float s = (MODE == 0) ? d * d : d;
        uint4 su = *(const uint4*)(hin + (size_t)node * OUT_CH + ch);
        float2 f;
        f = __half22float2(*(__half2*)&su.x); acc[0] += f.x; acc[1] += f.y;
        f = __half22float2(*(__half2*)&su.y); acc[2] += f.x; acc[3] += f.y;
        f = __half22float2(*(__half2*)&su.z); acc[4] += f.x; acc[5] += f.y;
        f = __half22float2(*(__half2*)&su.w); acc[6] += f.x; acc[7] += f.y;
        #pragma unroll
        for (int i = 0; i < 8; i++) acc[i] *= s;

        if (MODE == 0) {
            __half2 o[4];
            #pragma unroll
            for (int j = 0; j < 4; j++)
                o[j] = __floats2half2_rn(acc[2 * j], acc[2 * j + 1]);
            *(uint4*)(g_h1 + (size_t)node * OUT_CH + ch) = *(uint4*)o;
        } else {
            float* dst = outp + (size_t)node * OUT_CH + ch;
            *(float4*)(dst)     = make_float4(acc[0], acc[1], acc[2], acc[3]);
            *(float4*)(dst + 4) = make_float4(acc[4], acc[5], acc[6], acc[7]);
        }
    }
}

extern "C" void kernel_launch(void* const* d_in, const int* in_sizes, int n_in,
                              void* d_out, int out_size) {
    const void*  edge_index = d_in[0];               // [2, N_EDGES] int32 or int64
    const float* x          = (const float*)d_in[1]; // [N_NODES, 512]
    const float* W          = (const float*)d_in[2]; // [512, 64]
    float*       out        = (float*)d_out;         // [N_NODES, 64]

    cudaStream_t s1;
    cudaEvent_t  evRoot, evScan, evScale;
    cudaStreamCreateWithFlags(&s1, cudaStreamNonBlocking);
    cudaEventCreateWithFlags(&evRoot,  cudaEventDisableTiming);
    cudaEventCreateWithFlags(&evScan,  cudaEventDisableTiming);
    cudaEventCreateWithFlags(&evScale, cudaEventDisableTiming);

    cudaEventRecord(evRoot, 0);
    cudaStreamWaitEvent(s1, evRoot, 0);

    // s1: weight split + raw GEMM (needs only x, W)
    wsplit_kernel<<<(IN_CH * OUT_CH + 255) / 256, 256, 0, s1>>>(W);
    gemm_mma_kernel<<<(N_NODES + GBM - 1) / GBM, 256, 0, s1>>>(x);

    // s0: CSR build chain (2 edges per thread, fused zero+probe)
    zero_detect_kernel<<<(N_NODES + 255) / 256, 256>>>((const int*)edge_index);
    hist_kernel<<<(N_EDGES / 2 + 255) / 256, 256>>>(edge_index);
    scanA_kernel<<<SCAN_B, 1024>>>();
    scanB_kernel<<<1, 32>>>();
    scanC_kernel<<<SCAN_B, 1024>>>();
    cudaEventRecord(evScan, 0);

    // s1: scale_h0 (GEMM done on s1; scanC via event) — overlaps scatter
    cudaStreamWaitEvent(s1, evScan, 0);
    const int vec_total = N_NODES * OUT_CH / 4;
    scale_h0_kernel<<<(vec_total + 255) / 256, 256, 0, s1>>>();
    cudaEventRecord(evScale, s1);

    // s0: scatter ∥ scale_h0, then join and run the two hops
    scatter_kernel<<<(N_EDGES / 2 + 255) / 256, 256>>>(edge_index);
    cudaStreamWaitEvent(0, evScale, 0);

    const int blocks = (N_NODES * 32 + 255) / 256;
    gather_kernel<0><<<blocks, 256>>>(nullptr);
    gather_kernel<1><<<blocks, 256>>>(out);
}